// round 15
// baseline (speedup 1.0000x reference)
#include <cuda_runtime.h>
#include <cuda_bf16.h>
#include <math.h>
#include <stdint.h>

// ---------------- problem constants ----------------
constexpr int Bb = 4;
constexpr int Ss = 4096;
constexpr int Ee = 1024;
constexpr int Hh = 16;
constexpr int Dd = 64;
constexpr int Mtot = Bb * Ss;

constexpr int GEMM_SMEM = 73728;   // 3 stages x (16KB A + 8KB B)

// ---------------- scratch (device globals; device-code refs only) ----------------
__device__ __align__(16) float g_QH[(size_t)Mtot * Ee];
__device__ __align__(16) float g_KH[(size_t)Mtot * Ee];
__device__ __align__(16) float g_VH[(size_t)Mtot * Ee];
__device__ __align__(16) float g_ctx[Bb * Hh * Dd * Dd];
__device__ __align__(16) float g_kcum[Bb * Hh * Dd];
__device__ __align__(16) float g_mvec[Ee];
__device__ unsigned char g_qm[Mtot];
__device__ unsigned char g_km[Mtot];
__device__ int g_qidx[Mtot];
__device__ int g_kidx[Mtot];
__device__ int g_qoff[5];
__device__ int g_koff[5];
// per-input split-bf16 operand buffers (compact rows)
__device__ __align__(16) __nv_bfloat16 g_Qhi[(size_t)Mtot * Ee];
__device__ __align__(16) __nv_bfloat16 g_Qlo[(size_t)Mtot * Ee];
__device__ __align__(16) __nv_bfloat16 g_Khi[(size_t)Mtot * Ee];
__device__ __align__(16) __nv_bfloat16 g_Klo[(size_t)Mtot * Ee];
__device__ __align__(16) __nv_bfloat16 g_Vhi[(size_t)Mtot * Ee];
__device__ __align__(16) __nv_bfloat16 g_Vlo[(size_t)Mtot * Ee];
__device__ __align__(16) __nv_bfloat16 g_Wqhi[(size_t)Ee * Ee];
__device__ __align__(16) __nv_bfloat16 g_Wqlo[(size_t)Ee * Ee];
__device__ __align__(16) __nv_bfloat16 g_Wkhi[(size_t)Ee * Ee];
__device__ __align__(16) __nv_bfloat16 g_Wklo[(size_t)Ee * Ee];
__device__ __align__(16) __nv_bfloat16 g_Wvhi[(size_t)Ee * Ee];
__device__ __align__(16) __nv_bfloat16 g_Wvlo[(size_t)Ee * Ee];
__device__ __align__(16) __nv_bfloat16 g_Wphi[(size_t)Ee * Ee];
__device__ __align__(16) __nv_bfloat16 g_Wplo[(size_t)Ee * Ee];

// =====================================================================
// helpers
// =====================================================================
__device__ __forceinline__ uint32_t smem_u32(const void* p) {
    uint32_t a;
    asm("{ .reg .u64 t; cvta.to.shared.u64 t, %1; cvt.u32.u64 %0, t; }" : "=r"(a) : "l"(p));
    return a;
}
__device__ __forceinline__ uint32_t sw64(uint32_t off)  { return off ^ ((off >> 3) & 0x30); }
__device__ __forceinline__ uint32_t sw128(uint32_t off) { return off ^ ((off >> 3) & 0x70); }

#define CP_ASYNC16(dst, src) \
    asm volatile("cp.async.cg.shared.global [%0], [%1], 16;" :: "r"(dst), "l"(src))
#define CP_ASYNC16P(dst, src, sz) \
    asm volatile("cp.async.cg.shared.global [%0], [%1], 16, %2;" :: "r"(dst), "l"(src), "r"(sz))
#define CP_COMMIT() asm volatile("cp.async.commit_group;" ::: "memory")
#define CP_WAIT(N)  asm volatile("cp.async.wait_group %0;" :: "n"(N) : "memory")

#define LDSM4(r, addr)                                                            \
    asm volatile("ldmatrix.sync.aligned.m8n8.x4.shared.b16 {%0,%1,%2,%3}, [%4];"  \
        : "=r"((r)[0]), "=r"((r)[1]), "=r"((r)[2]), "=r"((r)[3]) : "r"(addr))

#define MMA_BF16(d, a, b0, b1)                                                    \
    asm volatile("mma.sync.aligned.m16n8k16.row.col.f32.bf16.bf16.f32 "           \
        "{%0,%1,%2,%3}, {%4,%5,%6,%7}, {%8,%9}, {%0,%1,%2,%3};"                   \
        : "+f"((d)[0]), "+f"((d)[1]), "+f"((d)[2]), "+f"((d)[3])                  \
        : "r"((a)[0]), "r"((a)[1]), "r"((a)[2]), "r"((a)[3]), "r"(b0), "r"(b1))

__device__ __forceinline__ void split4(float4 x, uint2& hv, uint2& lv) {
    __nv_bfloat16 h0 = __float2bfloat16(x.x), h1 = __float2bfloat16(x.y);
    __nv_bfloat16 h2 = __float2bfloat16(x.z), h3 = __float2bfloat16(x.w);
    __nv_bfloat16 l0 = __float2bfloat16(x.x - __bfloat162float(h0));
    __nv_bfloat16 l1 = __float2bfloat16(x.y - __bfloat162float(h1));
    __nv_bfloat16 l2 = __float2bfloat16(x.z - __bfloat162float(h2));
    __nv_bfloat16 l3 = __float2bfloat16(x.w - __bfloat162float(h3));
    __nv_bfloat162 a{h0, h1}, b{h2, h3}, c{l0, l1}, d{l2, l3};
    hv.x = *(uint32_t*)&a; hv.y = *(uint32_t*)&b;
    lv.x = *(uint32_t*)&c; lv.y = *(uint32_t*)&d;
}

// =====================================================================
// Mask normalization, both masks in one launch (blockIdx.y selects).
// =====================================================================
__global__ void norm_mask2(const unsigned char* __restrict__ qsrc,
                           const unsigned char* __restrict__ ksrc, int n)
{
    const unsigned char* src = blockIdx.y ? ksrc : qsrc;
    unsigned char* dst = blockIdx.y ? g_km : g_qm;
    __shared__ int vote_u8, any_nz;
    if (threadIdx.x == 0) { vote_u8 = 0; any_nz = 0; }
    __syncthreads();
    const unsigned int* w = (const unsigned int*)src;
    const int nw = n >> 2;
    int l_u8 = 0, l_nz = 0;
    for (int i = threadIdx.x; i < nw; i += blockDim.x) {
        unsigned int vv = w[i];
        if (vv != 0u) l_nz = 1;
        if (vv != 0u && vv != 1u && vv != 0x3F800000u) l_u8 = 1;
    }
    if (l_u8) vote_u8 = 1;
    if (l_nz) any_nz = 1;
    __syncthreads();
    if (!any_nz) {
        for (int i = threadIdx.x; i < n; i += blockDim.x) dst[i] = 0;
    } else if (vote_u8) {
        for (int i = threadIdx.x; i < n; i += blockDim.x) dst[i] = src[i] ? 1 : 0;
    } else {
        for (int i = threadIdx.x; i < n; i += blockDim.x) dst[i] = w[i] ? 1 : 0;
    }
}

// =====================================================================
// Deterministic compaction scan
// =====================================================================
__global__ void scan_kernel()
{
    __shared__ int qc[256], kc[256], qs[257], ks[257];
    const int t = threadIdx.x;
    int nq = 0, nk = 0;
#pragma unroll 4
    for (int i = 0; i < 64; i++) {
        nq += g_qm[t * 64 + i] ? 1 : 0;
        nk += g_km[t * 64 + i] ? 1 : 0;
    }
    qc[t] = nq; kc[t] = nk;
    __syncthreads();
    if (t == 0) {
        int aq = 0, ak = 0;
        for (int i = 0; i < 256; i++) { qs[i] = aq; ks[i] = ak; aq += qc[i]; ak += kc[i]; }
        qs[256] = aq; ks[256] = ak;
        for (int b = 0; b <= 4; b++) { g_qoff[b] = qs[b * 64]; g_koff[b] = ks[b * 64]; }
    }
    __syncthreads();
    int pq = qs[t], pk = ks[t];
    for (int i = 0; i < 64; i++) {
        const int r = t * 64 + i;
        if (g_qm[r]) g_qidx[pq++] = r;
        if (g_km[r]) g_kidx[pk++] = r;
    }
}

// =====================================================================
// All conversions in one launch. grid (2048, 4).
// =====================================================================
__global__ __launch_bounds__(256) void conv_all(
    const float* __restrict__ q, const float* __restrict__ k,
    const float* __restrict__ v,
    const float* __restrict__ Wq, const float* __restrict__ Wk,
    const float* __restrict__ Wv, const float* __restrict__ Wp)
{
    const int z = blockIdx.y;
    if (z < 3) {
        const int cnt = (z == 0) ? g_qoff[4] : g_koff[4];
        const int ci = blockIdx.x * 8 + (threadIdx.x >> 5);
        if (ci >= cnt) return;
        const int orig = (z == 0) ? g_qidx[ci] : g_kidx[ci];
        const float* __restrict__ src = (z == 0) ? q : (z == 1) ? k : v;
        __nv_bfloat16* hi = (z == 0) ? g_Qhi : (z == 1) ? g_Khi : g_Vhi;
        __nv_bfloat16* lo = (z == 0) ? g_Qlo : (z == 1) ? g_Klo : g_Vlo;
        const int lane = threadIdx.x & 31;
        const float4* s = (const float4*)(src + (size_t)orig * Ee);
        hi += (size_t)ci * Ee;
        lo += (size_t)ci * Ee;
        float4 xs[8];
#pragma unroll
        for (int j = 0; j < 8; j++) xs[j] = s[lane + j * 32];
#pragma unroll
        for (int j = 0; j < 8; j++) {
            uint2 hv, lv;
            split4(xs[j], hv, lv);
            *(uint2*)&hi[(lane + j * 32) * 4] = hv;
            *(uint2*)&lo[(lane + j * 32) * 4] = lv;
        }
    } else {
        const int bx = blockIdx.x;
        if (bx >= 512) return;
        const int wsel = bx >> 7;
        const float* __restrict__ W =
            (wsel == 0) ? Wq : (wsel == 1) ? Wk : (wsel == 2) ? Wv : Wp;
        __nv_bfloat16* hi =
            (wsel == 0) ? g_Wqhi : (wsel == 1) ? g_Wkhi : (wsel == 2) ? g_Wvhi : g_Wphi;
        __nv_bfloat16* lo =
            (wsel == 0) ? g_Wqlo : (wsel == 1) ? g_Wklo : (wsel == 2) ? g_Wvlo : g_Wplo;
        const size_t base = (size_t)(bx & 127) * 256 + threadIdx.x;
        constexpr size_t stride = 128u * 256u;
        float4 xs[8];
#pragma unroll
        for (int it = 0; it < 8; it++)
            xs[it] = ((const float4*)W)[base + (size_t)it * stride];
#pragma unroll
        for (int it = 0; it < 8; it++) {
            const size_t i4 = base + (size_t)it * stride;
            uint2 hv, lv;
            split4(xs[it], hv, lv);
            *(uint2*)&hi[i4 * 4] = hv;
            *(uint2*)&lo[i4 * 4] = lv;
        }
    }
}

// =====================================================================
// GEMM body: 128x64 CTA tile, BK=64, 8 warps (4m x 2n), warp tile 32x32.
// 3-stage cp.async ring (A 16KB + B 8KB per stage, SW128 rows).
// Virtual K: 48 slabs of 64 (0..15 hi*hi, 16..31 hi*lo, 32..47 lo*hi).
// MODE: 0 = store direct; 2 = scatter-atomicAdd via qidx (split-K final).
// =====================================================================
template<int MODE>
__device__ __forceinline__ void gemm_body(
    const __nv_bfloat16* __restrict__ Ahi, const __nv_bfloat16* __restrict__ Alo,
    const __nv_bfloat16* __restrict__ Bhi, const __nv_bfloat16* __restrict__ Blo,
    const float* __restrict__ bias, float* __restrict__ C,
    int cnt, int bm, int bn, bool dosm, int s0lab, int s1lab, char* smraw)
{
    const int tid  = threadIdx.x;
    const int lane = tid & 31;
    const int wid  = tid >> 5;
    const int wm   = (wid >> 1) * 32;   // 4 m-groups
    const int wn   = (wid & 1) * 32;    // 2 n-groups

    const uint32_t smA0 = smem_u32(smraw);       // 3 x 16KB
    const uint32_t smB0 = smA0 + 49152;          // 3 x 8KB

    // A loader: 128 rows x 128B; thread: row = tid>>1, 64B = 4 x 16B segs
    const int larow  = tid >> 1;
    const int laseg4 = (tid & 1) * 4;
    const uint32_t asz = (bm + larow < cnt) ? 16u : 0u;
    // B loader: 64 rows x 128B; thread: row = tid>>2, 32B = 2 x 16B segs
    const int lbrow  = tid >> 2;
    const int lbseg2 = (tid & 3) * 2;

    float acc[2][4][4];
#pragma unroll
    for (int mt = 0; mt < 2; mt++)
#pragma unroll
        for (int nt = 0; nt < 4; nt++)
#pragma unroll
            for (int i = 0; i < 4; i++) acc[mt][nt][i] = 0.f;

    auto issue = [&](int s, int st) {
        const int prod = s >> 4;
        const __nv_bfloat16* __restrict__ Ab = (prod == 2) ? Alo : Ahi;
        const __nv_bfloat16* __restrict__ Bb = (prod == 1) ? Blo : Bhi;
        const int ks = (s & 15) * 64;
#pragma unroll
        for (int i = 0; i < 4; i++) {
            const int seg = laseg4 + i;
            const uint32_t so = sw128((uint32_t)(larow * 128 + seg * 16));
            CP_ASYNC16P(smA0 + st * 16384 + so,
                        Ab + (size_t)(bm + larow) * Ee + ks + seg * 8, asz);
        }
#pragma unroll
        for (int i = 0; i < 2; i++) {
            const int seg = lbseg2 + i;
            const uint32_t so = sw128((uint32_t)(lbrow * 128 + seg * 16));
            CP_ASYNC16(smB0 + st * 8192 + so,
                       Bb + (size_t)(bn + lbrow) * Ee + ks + seg * 8);
        }
        CP_COMMIT();
    };

    issue(s0lab, 0);
    issue(s0lab + 1, 1);

    const int q = lane >> 3, r = lane & 7;

#pragma unroll 1
    for (int s = s0lab; s < s1lab; s++) {
        if (s < s1lab - 1) { CP_WAIT(1); } else { CP_WAIT(0); }
        __syncthreads();
        const int si = s - s0lab;
        const int st = si % 3;
        const uint32_t aB = smA0 + st * 16384;
        const uint32_t bB = smB0 + st * 8192;
#pragma unroll
        for (int kk = 0; kk < 64; kk += 16) {
            uint32_t afr[2][4], bfr[2][4];
#pragma unroll
            for (int mt = 0; mt < 2; mt++) {
                const int row = wm + mt * 16 + (q & 1) * 8 + r;
                LDSM4(afr[mt], aB + sw128((uint32_t)(row * 128 + kk * 2 + (q >> 1) * 16)));
            }
            {
                const int rowb = wn + q * 8 + r;
                LDSM4(bfr[0], bB + sw128((uint32_t)(rowb * 128 + kk * 2)));
                LDSM4(bfr[1], bB + sw128((uint32_t)(rowb * 128 + kk * 2 + 16)));
            }
#pragma unroll
            for (int mt = 0; mt < 2; mt++)
#pragma unroll
                for (int nt = 0; nt < 4; nt++)
                    MMA_BF16(acc[mt][nt], afr[mt], bfr[0][nt], bfr[1][nt]);
        }
        if (s + 2 < s1lab) issue(s + 2, (si + 2) % 3);
    }

    // ---- epilogue ----
    __syncthreads();

    const int cl = 2 * (lane & 3);
    if (MODE != 2) {
#pragma unroll
        for (int nt = 0; nt < 4; nt++) {
            const float2 bb = *(const float2*)&bias[bn + wn + nt * 8 + cl];
#pragma unroll
            for (int mt = 0; mt < 2; mt++) {
                acc[mt][nt][0] += bb.x; acc[mt][nt][1] += bb.y;
                acc[mt][nt][2] += bb.x; acc[mt][nt][3] += bb.y;
            }
        }
    }

    if (dosm) {
        // warp pair (wid, wid^1) shares rows wm..wm+31; cols split 32/32.
        float* redmax = (float*)smraw;          // [8 warps][32 rows]
        float* redsum = redmax + 256;
        const int rbase = (lane >> 2);
        float inv[2][2];
#pragma unroll
        for (int mt = 0; mt < 2; mt++)
#pragma unroll
            for (int hf = 0; hf < 2; hf++) {
                float m = -3.4e38f;
#pragma unroll
                for (int nt = 0; nt < 4; nt++)
                    m = fmaxf(m, fmaxf(acc[mt][nt][2 * hf], acc[mt][nt][2 * hf + 1]));
                m = fmaxf(m, __shfl_xor_sync(0xffffffffu, m, 1));
                m = fmaxf(m, __shfl_xor_sync(0xffffffffu, m, 2));
                if ((lane & 3) == 0)
                    redmax[wid * 32 + mt * 16 + hf * 8 + rbase] = m;
            }
        __syncthreads();
#pragma unroll
        for (int mt = 0; mt < 2; mt++)
#pragma unroll
            for (int hf = 0; hf < 2; hf++) {
                const int idx = mt * 16 + hf * 8 + rbase;
                const float rm = fmaxf(redmax[wid * 32 + idx],
                                       redmax[(wid ^ 1) * 32 + idx]);
                float s = 0.f;
#pragma unroll
                for (int nt = 0; nt < 4; nt++) {
                    float a0 = __expf(acc[mt][nt][2 * hf]     - rm);
                    float a1 = __expf(acc[mt][nt][2 * hf + 1] - rm);
                    acc[mt][nt][2 * hf] = a0; acc[mt][nt][2 * hf + 1] = a1;
                    s += a0 + a1;
                }
                s += __shfl_xor_sync(0xffffffffu, s, 1);
                s += __shfl_xor_sync(0xffffffffu, s, 2);
                if ((lane & 3) == 0)
                    redsum[wid * 32 + idx] = s;
            }
        __syncthreads();
#pragma unroll
        for (int mt = 0; mt < 2; mt++)
#pragma unroll
            for (int hf = 0; hf < 2; hf++) {
                const int idx = mt * 16 + hf * 8 + rbase;
                inv[mt][hf] = 1.f / (redsum[wid * 32 + idx] +
                                     redsum[(wid ^ 1) * 32 + idx]);
            }
#pragma unroll
        for (int mt = 0; mt < 2; mt++)
#pragma unroll
            for (int nt = 0; nt < 4; nt++) {
                acc[mt][nt][0] *= inv[mt][0]; acc[mt][nt][1] *= inv[mt][0];
                acc[mt][nt][2] *= inv[mt][1]; acc[mt][nt][3] *= inv[mt][1];
            }
    }

#pragma unroll
    for (int mt = 0; mt < 2; mt++) {
        const int row0 = bm + wm + mt * 16 + (lane >> 2);
        const int row1 = row0 + 8;
#pragma unroll
        for (int nt = 0; nt < 4; nt++) {
            const int col = bn + wn + nt * 8 + cl;
            if (MODE == 0) {
                if (row0 < cnt) {
                    float2 o0{acc[mt][nt][0], acc[mt][nt][1]};
                    *(float2*)&C[(size_t)row0 * Ee + col] = o0;
                }
                if (row1 < cnt) {
                    float2 o1{acc[mt][nt][2], acc[mt][nt][3]};
                    *(float2*)&C[(size_t)row1 * Ee + col] = o1;
                }
            } else {
                if (row0 < cnt) {
                    float* p = &C[(size_t)g_qidx[row0] * Ee + col];
                    atomicAdd(p, acc[mt][nt][0]);
                    atomicAdd(p + 1, acc[mt][nt][1]);
                }
                if (row1 < cnt) {
                    float* p = &C[(size_t)g_qidx[row1] * Ee + col];
                    atomicAdd(p, acc[mt][nt][2]);
                    atomicAdd(p + 1, acc[mt][nt][3]);
                }
            }
        }
    }
}

// batched QKV projection GEMM: z = 0 Q(softmax), 1 K(softmax), 2 V(plain)
__global__ __launch_bounds__(256, 3) void tgemm_qkv(
    const float* __restrict__ bq, const float* __restrict__ bk,
    const float* __restrict__ bv)
{
    extern __shared__ __align__(128) char smraw[];
    const int z = blockIdx.z;
    const int cnt = (z == 0) ? g_qoff[4] : g_koff[4];
    const int bm = blockIdx.y * 128;
    if (bm >= cnt) return;
    const int bn = blockIdx.x * 64;
    const __nv_bfloat16* Ahi = (z == 0) ? g_Qhi : (z == 1) ? g_Khi : g_Vhi;
    const __nv_bfloat16* Alo = (z == 0) ? g_Qlo : (z == 1) ? g_Klo : g_Vlo;
    const __nv_bfloat16* Bhi = (z == 0) ? g_Wqhi : (z == 1) ? g_Wkhi : g_Wvhi;
    const __nv_bfloat16* Blo = (z == 0) ? g_Wqlo : (z == 1) ? g_Wklo : g_Wvlo;
    const float* bias = (z == 0) ? bq : (z == 1) ? bk : bv;
    float* C = (z == 0) ? g_QH : (z == 1) ? g_KH : g_VH;
    gemm_body<0>(Ahi, Alo, Bhi, Blo, bias, C, cnt, bm, bn,
                 /*dosm=*/z != 2, 0, 48, smraw);
}

// final output-projection GEMM: split-K x2 (z = k-half), atomicAdd scatter.
__global__ __launch_bounds__(256, 3) void tgemm_fin(float* __restrict__ Cext)
{
    extern __shared__ __align__(128) char smraw[];
    const int cnt = g_qoff[4];
    const int bm = blockIdx.y * 128;
    if (bm >= cnt) return;
    const int s0lab = blockIdx.z * 24;
    gemm_body<2>(g_Qhi, g_Qlo, g_Wphi, g_Wplo, nullptr, Cext, cnt, bm,
                 blockIdx.x * 64, false, s0lab, s0lab + 24, smraw);
}

// =====================================================================
// misc: y=0 khmask rowsums (first 128 blocks), y=1 zero masked out rows,
//       y=2 bias-init unmasked out rows. grid (2048, 3).
// =====================================================================
__global__ __launch_bounds__(256) void misc_kernel(
    const float* __restrict__ Wk, const float* __restrict__ bk,
    const float* __restrict__ bp, float* __restrict__ out)
{
    const int y = blockIdx.y;
    if (y == 0) {
        if (blockIdx.x >= 128) return;
        const int r = blockIdx.x * 8 + (threadIdx.x >> 5);
        const int lane = threadIdx.x & 31;
        float s = 0.f;
        for (int e = lane; e < Ee; e += 32) s += Wk[(size_t)r * Ee + e];
#pragma unroll
        for (int o = 16; o; o >>= 1) s += __shfl_xor_sync(0xffffffffu, s, o);
        if (lane == 0) g_mvec[r] = -1e9f * s + bk[r];
    } else if (y == 1) {
        const int row = blockIdx.x * 8 + (threadIdx.x >> 5);
        if (g_qm[row]) return;
        const int lane = threadIdx.x & 31;
        const float4 z{0.f, 0.f, 0.f, 0.f};
        float4* o = (float4*)(out + (size_t)row * Ee);
#pragma unroll
        for (int j = 0; j < 8; j++) o[lane + j * 32] = z;
    } else {
        const int ci = blockIdx.x * 8 + (threadIdx.x >> 5);
        if (ci >= g_qoff[4]) return;
        const int row = g_qidx[ci];
        const int lane = threadIdx.x & 31;
        float4* o = (float4*)(out + (size_t)row * Ee);
        const float4* b = (const float4*)bp;
#pragma unroll
        for (int j = 0; j < 8; j++) o[lane + j * 32] = b[lane + j * 32];
    }
}

// =====================================================================
// init ctx/kcum with analytic masked-row corrections (local khm softmax)
// =====================================================================
__global__ void init_ctx(const float* __restrict__ bv)
{
    const int bh = blockIdx.x;
    const int b = bh >> 4, h = bh & 15;
    __shared__ float khm[Dd];
    if (threadIdx.x == 0) {
        float mx = -3.4e38f;
        for (int d = 0; d < Dd; d++) mx = fmaxf(mx, g_mvec[h * Dd + d]);
        float sm = 0.f;
        for (int d = 0; d < Dd; d++) sm += expf(g_mvec[h * Dd + d] - mx);
        const float inv = 1.f / sm;
        for (int d = 0; d < Dd; d++) khm[d] = expf(g_mvec[h * Dd + d] - mx) * inv;
    }
    __syncthreads();
    const float nm = (float)(Ss - (g_koff[b + 1] - g_koff[b]));
    for (int i = threadIdx.x; i < Dd * Dd; i += 256) {
        const int d = i >> 6, e = i & 63;
        g_ctx[bh * Dd * Dd + i] = nm * khm[d] * bv[h * Dd + e];
    }
    if (threadIdx.x < 64)
        g_kcum[bh * Dd + threadIdx.x] = nm * khm[threadIdx.x];
}

// =====================================================================
// context over compacted per-batch segment; folds kcum.
// =====================================================================
__global__ __launch_bounds__(256) void context_kernel()
{
    const int bh = blockIdx.y;
    const int b = bh >> 4, h = bh & 15;
    const int base = g_koff[b];
    const int cntb = g_koff[b + 1] - base;
    const int s0 = blockIdx.x * 256;
    if (s0 >= cntb) return;

    __shared__ __align__(16) float kh[3][16][64];
    __shared__ __align__(16) float vh[3][16][64];

    const int tid  = threadIdx.x;
    const int dB   = (tid >> 4) * 4;
    const int eB   = (tid & 15) * 4;
    const int lrow = tid >> 4;
    const int lseg = tid & 15;
    const uint32_t kB = smem_u32(&kh[0][0][0]);
    const uint32_t vB = smem_u32(&vh[0][0][0]);

    auto issue = [&](int t, int st) {
        const int row = s0 + t * 16 + lrow;
        const uint32_t sz = (row < cntb) ? 16u : 0u;
        const int rc = (row < cntb) ? row : 0;
        const size_t g = ((size_t)(base + rc)) * Ee + h * Dd + lseg * 4;
        CP_ASYNC16P(kB + st * 4096 + lrow * 256 + lseg * 16, g_KH + g, sz);
        CP_ASYNC16P(vB + st * 4096 + lrow * 256 + lseg * 16, g_VH + g, sz);
        CP_COMMIT();
    };

    float acc[4][4];
#pragma unroll
    for (int i = 0; i < 4; i++)
#pragma unroll
        for (int l = 0; l < 4; l++) acc[i][l] = 0.f;
    float kcp[4] = {0.f, 0.f, 0.f, 0.f};

    issue(0, 0);
    issue(1, 1);
#pragma unroll 1
    for (int t = 0; t < 16; t++) {
        if (t < 15) { CP_WAIT(1); } else { CP_WAIT(0); }
        __syncthreads();
        const int st = t % 3;
#pragma unroll
        for (int j = 0; j < 16; j++) {
            const float4 kv = *(const float4*)&kh[st][j][dB];
            const float4 vv = *(const float4*)&vh[st][j][eB];
            kcp[0] += kv.x; kcp[1] += kv.y; kcp[2] += kv.z; kcp[3] += kv.w;
            acc[0][0] += kv.x * vv.x; acc[0][1] += kv.x * vv.y;
            acc[0][2] += kv.x * vv.z; acc[0][3] += kv.x * vv.w;
            acc[1][0] += kv.y * vv.x; acc[1][1] += kv.y * vv.y;
            acc[1][2] += kv.y * vv.z; acc[1][3] += kv.y * vv.w;
            acc[2][0] += kv.z * vv.x; acc[2][1] += kv.z * vv.y;
            acc[2][2] += kv.z * vv.z; acc[2][3] += kv.z * vv.w;
            acc[3][0] += kv.w * vv.x; acc[3][1] += kv.w * vv.y;
            acc[3][2] += kv.w * vv.z; acc[3][3] += kv.w * vv.w;
        }
        if (t + 2 < 16) issue(t + 2, (t + 2) % 3);
    }

    float* ctx = g_ctx + (size_t)bh * Dd * Dd;
#pragma unroll
    for (int i = 0; i < 4; i++)
#pragma unroll
        for (int l = 0; l < 4; l++)
            atomicAdd(&ctx[(dB + i) * Dd + eB + l], acc[i][l]);
    if ((tid & 15) == 0) {
#pragma unroll
        for (int i = 0; i < 4; i++)
            atomicAdd(&g_kcum[bh * Dd + dB + i], kcp[i]);
    }
}

// =====================================================================
// combine over compacted q rows; emits hi/lo bf16 into g_Qhi/g_Qlo.
// =====================================================================
__global__ __launch_bounds__(256) void combine_kernel()
{
    const int bh = blockIdx.y;
    const int b = bh >> 4, h = bh & 15;
    const int base = g_qoff[b];
    const int cntb = g_qoff[b + 1] - base;
    const int s0 = blockIdx.x * 128;
    if (s0 >= cntb) return;

    __shared__ float ctx[64][64];
    __shared__ float kc[64];
    for (int i = threadIdx.x; i < Dd * Dd; i += 256)
        ((float*)ctx)[i] = g_ctx[(size_t)bh * Dd * Dd + i];
    if (threadIdx.x < 64) kc[threadIdx.x] = g_kcum[bh * Dd + threadIdx.x];
    __syncthreads();

    const int warp = threadIdx.x >> 5, lane = threadIdx.x & 31;
    const int lim = (s0 + 128 < cntb) ? (s0 + 128) : cntb;
    for (int s = s0 + warp; s < lim; s += 8) {
        const size_t gi = ((size_t)(base + s)) * Ee + h * Dd;
        const float* p = g_QH + gi;
        const float q0 = p[lane], q1 = p[lane + 32];
        float dot = q0 * kc[lane] + q1 * kc[lane + 32];
#pragma unroll
        for (int o = 16; o; o >>= 1) dot += __shfl_xor_sync(0xffffffffu, dot, o);
        const float a = 1.f / dot;
        float o0 = 0.f, o1 = 0.f;
#pragma unroll
        for (int d = 0; d < 32; d++) {
            const float qd = __shfl_sync(0xffffffffu, q0, d);
            o0 += qd * ctx[d][lane];
            o1 += qd * ctx[d][lane + 32];
        }
#pragma unroll
        for (int d = 0; d < 32; d++) {
            const float qd = __shfl_sync(0xffffffffu, q1, d);
            o0 += qd * ctx[d + 32][lane];
            o1 += qd * ctx[d + 32][lane + 32];
        }
        const float r0 = o0 * a + q0;
        const float r1 = o1 * a + q1;
        __nv_bfloat16 h0 = __float2bfloat16(r0);
        __nv_bfloat16 h1 = __float2bfloat16(r1);
        g_Qhi[gi + lane]      = h0;
        g_Qhi[gi + lane + 32] = h1;
        g_Qlo[gi + lane]      = __float2bfloat16(r0 - __bfloat162float(h0));
        g_Qlo[gi + lane + 32] = __float2bfloat16(r1 - __bfloat162float(h1));
    }
}

// =====================================================================
extern "C" void kernel_launch(void* const* d_in, const int* in_sizes, int n_in,
                              void* d_out, int out_size)
{
    const float* q  = (const float*)d_in[0];
    const float* k  = (const float*)d_in[1];
    const float* v  = (const float*)d_in[2];
    const unsigned char* qm_raw = (const unsigned char*)d_in[3];
    const unsigned char* km_raw = (const unsigned char*)d_in[4];
    const float* Wq = (const float*)d_in[5];
    const float* bq = (const float*)d_in[6];
    const float* Wk = (const float*)d_in[7];
    const float* bk = (const float*)d_in[8];
    const float* Wv = (const float*)d_in[9];
    const float* bv = (const float*)d_in[10];
    const float* Wp = (const float*)d_in[11];
    const float* bp = (const float*)d_in[12];
    float* out = (float*)d_out;

    cudaFuncSetAttribute(tgemm_qkv, cudaFuncAttributeMaxDynamicSharedMemorySize, GEMM_SMEM);
    cudaFuncSetAttribute(tgemm_fin, cudaFuncAttributeMaxDynamicSharedMemorySize, GEMM_SMEM);

    // 1-2) masks + compaction lists
    norm_mask2<<<dim3(1, 2), 1024>>>(qm_raw, km_raw, Mtot);
    scan_kernel<<<1, 256>>>();

    // 3) all conversions in one launch
    conv_all<<<dim3(2048, 4), 256>>>(q, k, v, Wq, Wk, Wv, Wp);

    // 4) batched QKV GEMM (128x64 tiles, BK=64, 3 CTAs/SM)  <-- profiled
    tgemm_qkv<<<dim3(16, 128, 3), 256, GEMM_SMEM>>>(bq, bk, bv);

    // 5-6) masked-row analytics + output base (bias / zeros), then ctx init
    misc_kernel<<<dim3(2048, 3), 256>>>(Wk, bk, bp, out);
    init_ctx<<<Bb * Hh, 256>>>(bv);

    // 7-8) linear-attention core
    context_kernel<<<dim3(16, Bb * Hh), 256>>>();
    combine_kernel<<<dim3(32, Bb * Hh), 256>>>();

    // 9) output projection: split-K x2, atomicAdd scatter onto bias base
    tgemm_fin<<<dim3(16, 128, 2), 256, GEMM_SMEM>>>(out);
}

// round 16
// speedup vs baseline: 1.0119x; 1.0119x over previous
#include <cuda_runtime.h>
#include <cuda_bf16.h>
#include <math.h>
#include <stdint.h>

// ---------------- problem constants ----------------
constexpr int Bb = 4;
constexpr int Ss = 4096;
constexpr int Ee = 1024;
constexpr int Hh = 16;
constexpr int Dd = 64;
constexpr int Mtot = Bb * Ss;

constexpr int GEMM_SMEM = 49152;   // 4 stages x (8KB A + 4KB B)

// ---------------- scratch (device globals; device-code refs only) ----------------
__device__ __align__(16) float g_QH[(size_t)Mtot * Ee];
__device__ __align__(16) float g_KH[(size_t)Mtot * Ee];
__device__ __align__(16) float g_VH[(size_t)Mtot * Ee];
__device__ __align__(16) float g_ctx[Bb * Hh * Dd * Dd];
__device__ __align__(16) float g_kcum[Bb * Hh * Dd];
__device__ __align__(16) float g_mvec[Ee];
__device__ unsigned char g_qm[Mtot];
__device__ unsigned char g_km[Mtot];
__device__ int g_qidx[Mtot];
__device__ int g_kidx[Mtot];
__device__ int g_qoff[5];
__device__ int g_koff[5];
// per-input split-bf16 operand buffers (compact rows)
__device__ __align__(16) __nv_bfloat16 g_Qhi[(size_t)Mtot * Ee];
__device__ __align__(16) __nv_bfloat16 g_Qlo[(size_t)Mtot * Ee];
__device__ __align__(16) __nv_bfloat16 g_Khi[(size_t)Mtot * Ee];
__device__ __align__(16) __nv_bfloat16 g_Klo[(size_t)Mtot * Ee];
__device__ __align__(16) __nv_bfloat16 g_Vhi[(size_t)Mtot * Ee];
__device__ __align__(16) __nv_bfloat16 g_Vlo[(size_t)Mtot * Ee];
__device__ __align__(16) __nv_bfloat16 g_Wqhi[(size_t)Ee * Ee];
__device__ __align__(16) __nv_bfloat16 g_Wqlo[(size_t)Ee * Ee];
__device__ __align__(16) __nv_bfloat16 g_Wkhi[(size_t)Ee * Ee];
__device__ __align__(16) __nv_bfloat16 g_Wklo[(size_t)Ee * Ee];
__device__ __align__(16) __nv_bfloat16 g_Wvhi[(size_t)Ee * Ee];
__device__ __align__(16) __nv_bfloat16 g_Wvlo[(size_t)Ee * Ee];
__device__ __align__(16) __nv_bfloat16 g_Wphi[(size_t)Ee * Ee];
__device__ __align__(16) __nv_bfloat16 g_Wplo[(size_t)Ee * Ee];

// =====================================================================
// helpers
// =====================================================================
__device__ __forceinline__ uint32_t smem_u32(const void* p) {
    uint32_t a;
    asm("{ .reg .u64 t; cvta.to.shared.u64 t, %1; cvt.u32.u64 %0, t; }" : "=r"(a) : "l"(p));
    return a;
}
__device__ __forceinline__ uint32_t sw64(uint32_t off) { return off ^ ((off >> 3) & 0x30); }

#define CP_ASYNC16(dst, src) \
    asm volatile("cp.async.cg.shared.global [%0], [%1], 16;" :: "r"(dst), "l"(src))
#define CP_ASYNC16P(dst, src, sz) \
    asm volatile("cp.async.cg.shared.global [%0], [%1], 16, %2;" :: "r"(dst), "l"(src), "r"(sz))
#define CP_COMMIT() asm volatile("cp.async.commit_group;" ::: "memory")
#define CP_WAIT(N)  asm volatile("cp.async.wait_group %0;" :: "n"(N) : "memory")

#define LDSM4(r, addr)                                                            \
    asm volatile("ldmatrix.sync.aligned.m8n8.x4.shared.b16 {%0,%1,%2,%3}, [%4];"  \
        : "=r"((r)[0]), "=r"((r)[1]), "=r"((r)[2]), "=r"((r)[3]) : "r"(addr))

#define MMA_BF16(d, a, b0, b1)                                                    \
    asm volatile("mma.sync.aligned.m16n8k16.row.col.f32.bf16.bf16.f32 "           \
        "{%0,%1,%2,%3}, {%4,%5,%6,%7}, {%8,%9}, {%0,%1,%2,%3};"                   \
        : "+f"((d)[0]), "+f"((d)[1]), "+f"((d)[2]), "+f"((d)[3])                  \
        : "r"((a)[0]), "r"((a)[1]), "r"((a)[2]), "r"((a)[3]), "r"(b0), "r"(b1))

__device__ __forceinline__ void split4(float4 x, uint2& hv, uint2& lv) {
    __nv_bfloat16 h0 = __float2bfloat16(x.x), h1 = __float2bfloat16(x.y);
    __nv_bfloat16 h2 = __float2bfloat16(x.z), h3 = __float2bfloat16(x.w);
    __nv_bfloat16 l0 = __float2bfloat16(x.x - __bfloat162float(h0));
    __nv_bfloat16 l1 = __float2bfloat16(x.y - __bfloat162float(h1));
    __nv_bfloat16 l2 = __float2bfloat16(x.z - __bfloat162float(h2));
    __nv_bfloat16 l3 = __float2bfloat16(x.w - __bfloat162float(h3));
    __nv_bfloat162 a{h0, h1}, b{h2, h3}, c{l0, l1}, d{l2, l3};
    hv.x = *(uint32_t*)&a; hv.y = *(uint32_t*)&b;
    lv.x = *(uint32_t*)&c; lv.y = *(uint32_t*)&d;
}

// =====================================================================
// Mask normalization, both masks in one launch (blockIdx.y selects).
// =====================================================================
__global__ void norm_mask2(const unsigned char* __restrict__ qsrc,
                           const unsigned char* __restrict__ ksrc, int n)
{
    const unsigned char* src = blockIdx.y ? ksrc : qsrc;
    unsigned char* dst = blockIdx.y ? g_km : g_qm;
    __shared__ int vote_u8, any_nz;
    if (threadIdx.x == 0) { vote_u8 = 0; any_nz = 0; }
    __syncthreads();
    const unsigned int* w = (const unsigned int*)src;
    const int nw = n >> 2;
    int l_u8 = 0, l_nz = 0;
    for (int i = threadIdx.x; i < nw; i += blockDim.x) {
        unsigned int vv = w[i];
        if (vv != 0u) l_nz = 1;
        if (vv != 0u && vv != 1u && vv != 0x3F800000u) l_u8 = 1;
    }
    if (l_u8) vote_u8 = 1;
    if (l_nz) any_nz = 1;
    __syncthreads();
    if (!any_nz) {
        for (int i = threadIdx.x; i < n; i += blockDim.x) dst[i] = 0;
    } else if (vote_u8) {
        for (int i = threadIdx.x; i < n; i += blockDim.x) dst[i] = src[i] ? 1 : 0;
    } else {
        for (int i = threadIdx.x; i < n; i += blockDim.x) dst[i] = w[i] ? 1 : 0;
    }
}

// =====================================================================
// Deterministic compaction scan
// =====================================================================
__global__ void scan_kernel()
{
    __shared__ int qc[256], kc[256], qs[257], ks[257];
    const int t = threadIdx.x;
    int nq = 0, nk = 0;
#pragma unroll 4
    for (int i = 0; i < 64; i++) {
        nq += g_qm[t * 64 + i] ? 1 : 0;
        nk += g_km[t * 64 + i] ? 1 : 0;
    }
    qc[t] = nq; kc[t] = nk;
    __syncthreads();
    if (t == 0) {
        int aq = 0, ak = 0;
        for (int i = 0; i < 256; i++) { qs[i] = aq; ks[i] = ak; aq += qc[i]; ak += kc[i]; }
        qs[256] = aq; ks[256] = ak;
        for (int b = 0; b <= 4; b++) { g_qoff[b] = qs[b * 64]; g_koff[b] = ks[b * 64]; }
    }
    __syncthreads();
    int pq = qs[t], pk = ks[t];
    for (int i = 0; i < 64; i++) {
        const int r = t * 64 + i;
        if (g_qm[r]) g_qidx[pq++] = r;
        if (g_km[r]) g_kidx[pk++] = r;
    }
}

// =====================================================================
// All conversions in one launch. grid (2048, 4).
// =====================================================================
__global__ __launch_bounds__(256) void conv_all(
    const float* __restrict__ q, const float* __restrict__ k,
    const float* __restrict__ v,
    const float* __restrict__ Wq, const float* __restrict__ Wk,
    const float* __restrict__ Wv, const float* __restrict__ Wp)
{
    const int z = blockIdx.y;
    if (z < 3) {
        const int cnt = (z == 0) ? g_qoff[4] : g_koff[4];
        const int ci = blockIdx.x * 8 + (threadIdx.x >> 5);
        if (ci >= cnt) return;
        const int orig = (z == 0) ? g_qidx[ci] : g_kidx[ci];
        const float* __restrict__ src = (z == 0) ? q : (z == 1) ? k : v;
        __nv_bfloat16* hi = (z == 0) ? g_Qhi : (z == 1) ? g_Khi : g_Vhi;
        __nv_bfloat16* lo = (z == 0) ? g_Qlo : (z == 1) ? g_Klo : g_Vlo;
        const int lane = threadIdx.x & 31;
        const float4* s = (const float4*)(src + (size_t)orig * Ee);
        hi += (size_t)ci * Ee;
        lo += (size_t)ci * Ee;
        float4 xs[8];
#pragma unroll
        for (int j = 0; j < 8; j++) xs[j] = s[lane + j * 32];
#pragma unroll
        for (int j = 0; j < 8; j++) {
            uint2 hv, lv;
            split4(xs[j], hv, lv);
            *(uint2*)&hi[(lane + j * 32) * 4] = hv;
            *(uint2*)&lo[(lane + j * 32) * 4] = lv;
        }
    } else {
        const int bx = blockIdx.x;
        if (bx >= 512) return;
        const int wsel = bx >> 7;
        const float* __restrict__ W =
            (wsel == 0) ? Wq : (wsel == 1) ? Wk : (wsel == 2) ? Wv : Wp;
        __nv_bfloat16* hi =
            (wsel == 0) ? g_Wqhi : (wsel == 1) ? g_Wkhi : (wsel == 2) ? g_Wvhi : g_Wphi;
        __nv_bfloat16* lo =
            (wsel == 0) ? g_Wqlo : (wsel == 1) ? g_Wklo : (wsel == 2) ? g_Wvlo : g_Wplo;
        const size_t base = (size_t)(bx & 127) * 256 + threadIdx.x;
        constexpr size_t stride = 128u * 256u;
        float4 xs[8];
#pragma unroll
        for (int it = 0; it < 8; it++)
            xs[it] = ((const float4*)W)[base + (size_t)it * stride];
#pragma unroll
        for (int it = 0; it < 8; it++) {
            const size_t i4 = base + (size_t)it * stride;
            uint2 hv, lv;
            split4(xs[it], hv, lv);
            *(uint2*)&hi[i4 * 4] = hv;
            *(uint2*)&lo[i4 * 4] = lv;
        }
    }
}

// =====================================================================
// GEMM body: 128x64 CTA tile, BK=32, 8 warps (4m x 2n), warp tile 32x32.
// 4-stage cp.async ring (A 8KB + B 4KB per stage). Virtual K slabs [s0,s1).
// MODE: 0 = store direct; 2 = scatter-atomicAdd via qidx (split-K final).
// =====================================================================
template<int MODE>
__device__ __forceinline__ void gemm_body(
    const __nv_bfloat16* __restrict__ Ahi, const __nv_bfloat16* __restrict__ Alo,
    const __nv_bfloat16* __restrict__ Bhi, const __nv_bfloat16* __restrict__ Blo,
    const float* __restrict__ bias, float* __restrict__ C,
    int cnt, int bm, int bn, bool dosm, int s0lab, int s1lab, char* smraw)
{
    const int tid  = threadIdx.x;
    const int lane = tid & 31;
    const int wid  = tid >> 5;
    const int wm   = (wid >> 1) * 32;   // 4 m-groups
    const int wn   = (wid & 1) * 32;    // 2 n-groups

    const uint32_t smA0 = smem_u32(smraw);       // 4 x 8KB
    const uint32_t smB0 = smA0 + 32768;          // 4 x 4KB

    // A loader: 128 rows x 4 segs(16B) = 512 chunks -> 2/thread
    const int larow = tid >> 1;
    const int laseg = (tid & 1) * 2;
    const uint32_t asz = (bm + larow < cnt) ? 16u : 0u;
    // B loader: 64 rows x 4 segs = 256 chunks -> 1/thread
    const int lbrow = tid >> 2;
    const int lbseg = tid & 3;

    float acc[2][4][4];
#pragma unroll
    for (int mt = 0; mt < 2; mt++)
#pragma unroll
        for (int nt = 0; nt < 4; nt++)
#pragma unroll
            for (int i = 0; i < 4; i++) acc[mt][nt][i] = 0.f;

    auto issue = [&](int s, int st) {
        const int prod = s >> 5;
        const __nv_bfloat16* __restrict__ Ab = (prod == 2) ? Alo : Ahi;
        const __nv_bfloat16* __restrict__ Bb = (prod == 1) ? Blo : Bhi;
        const int ks = (s & 31) * 32;
#pragma unroll
        for (int i = 0; i < 2; i++) {
            const int seg = laseg + i;
            const uint32_t so = sw64((uint32_t)(larow * 64 + seg * 16));
            CP_ASYNC16P(smA0 + st * 8192 + so,
                        Ab + (size_t)(bm + larow) * Ee + ks + seg * 8, asz);
        }
        {
            const uint32_t so = sw64((uint32_t)(lbrow * 64 + lbseg * 16));
            CP_ASYNC16(smB0 + st * 4096 + so,
                       Bb + (size_t)(bn + lbrow) * Ee + ks + lbseg * 8);
        }
        CP_COMMIT();
    };

    issue(s0lab, s0lab & 3);
    issue(s0lab + 1, (s0lab + 1) & 3);
    issue(s0lab + 2, (s0lab + 2) & 3);

    const int q = lane >> 3, r = lane & 7;

#pragma unroll 1
    for (int s = s0lab; s < s1lab; s++) {
        if (s < s1lab - 2) { CP_WAIT(2); }
        else if (s == s1lab - 2) { CP_WAIT(1); }
        else { CP_WAIT(0); }
        __syncthreads();
        const int st = s & 3;
        const uint32_t aB = smA0 + st * 8192;
        const uint32_t bB = smB0 + st * 4096;
#pragma unroll
        for (int kk = 0; kk < 32; kk += 16) {
            uint32_t afr[2][4], bfr[2][4];
#pragma unroll
            for (int mt = 0; mt < 2; mt++) {
                const int row = wm + mt * 16 + (q & 1) * 8 + r;
                LDSM4(afr[mt], aB + sw64((uint32_t)(row * 64 + kk * 2 + (q >> 1) * 16)));
            }
            {
                const int rowb = wn + q * 8 + r;
                LDSM4(bfr[0], bB + sw64((uint32_t)(rowb * 64 + kk * 2)));
                LDSM4(bfr[1], bB + sw64((uint32_t)(rowb * 64 + kk * 2 + 16)));
            }
#pragma unroll
            for (int mt = 0; mt < 2; mt++)
#pragma unroll
                for (int nt = 0; nt < 4; nt++)
                    MMA_BF16(acc[mt][nt], afr[mt], bfr[0][nt], bfr[1][nt]);
        }
        if (s + 3 < s1lab) issue(s + 3, (s + 3) & 3);
    }

    // ---- epilogue ----
    __syncthreads();

    const int cl = 2 * (lane & 3);
    if (MODE != 2) {
#pragma unroll
        for (int nt = 0; nt < 4; nt++) {
            const float2 bb = *(const float2*)&bias[bn + wn + nt * 8 + cl];
#pragma unroll
            for (int mt = 0; mt < 2; mt++) {
                acc[mt][nt][0] += bb.x; acc[mt][nt][1] += bb.y;
                acc[mt][nt][2] += bb.x; acc[mt][nt][3] += bb.y;
            }
        }
    }

    if (dosm) {
        // warp pair (wid, wid^1) shares rows wm..wm+31; cols split 32/32.
        float* redmax = (float*)smraw;          // [8 warps][32 rows]
        float* redsum = redmax + 256;
        const int rbase = (lane >> 2);
        float inv[2][2];
#pragma unroll
        for (int mt = 0; mt < 2; mt++)
#pragma unroll
            for (int hf = 0; hf < 2; hf++) {
                float m = -3.4e38f;
#pragma unroll
                for (int nt = 0; nt < 4; nt++)
                    m = fmaxf(m, fmaxf(acc[mt][nt][2 * hf], acc[mt][nt][2 * hf + 1]));
                m = fmaxf(m, __shfl_xor_sync(0xffffffffu, m, 1));
                m = fmaxf(m, __shfl_xor_sync(0xffffffffu, m, 2));
                if ((lane & 3) == 0)
                    redmax[wid * 32 + mt * 16 + hf * 8 + rbase] = m;
            }
        __syncthreads();
#pragma unroll
        for (int mt = 0; mt < 2; mt++)
#pragma unroll
            for (int hf = 0; hf < 2; hf++) {
                const int idx = mt * 16 + hf * 8 + rbase;
                const float rm = fmaxf(redmax[wid * 32 + idx],
                                       redmax[(wid ^ 1) * 32 + idx]);
                float s = 0.f;
#pragma unroll
                for (int nt = 0; nt < 4; nt++) {
                    float a0 = __expf(acc[mt][nt][2 * hf]     - rm);
                    float a1 = __expf(acc[mt][nt][2 * hf + 1] - rm);
                    acc[mt][nt][2 * hf] = a0; acc[mt][nt][2 * hf + 1] = a1;
                    s += a0 + a1;
                }
                s += __shfl_xor_sync(0xffffffffu, s, 1);
                s += __shfl_xor_sync(0xffffffffu, s, 2);
                if ((lane & 3) == 0)
                    redsum[wid * 32 + idx] = s;
            }
        __syncthreads();
#pragma unroll
        for (int mt = 0; mt < 2; mt++)
#pragma unroll
            for (int hf = 0; hf < 2; hf++) {
                const int idx = mt * 16 + hf * 8 + rbase;
                inv[mt][hf] = 1.f / (redsum[wid * 32 + idx] +
                                     redsum[(wid ^ 1) * 32 + idx]);
            }
#pragma unroll
        for (int mt = 0; mt < 2; mt++)
#pragma unroll
            for (int nt = 0; nt < 4; nt++) {
                acc[mt][nt][0] *= inv[mt][0]; acc[mt][nt][1] *= inv[mt][0];
                acc[mt][nt][2] *= inv[mt][1]; acc[mt][nt][3] *= inv[mt][1];
            }
    }

#pragma unroll
    for (int mt = 0; mt < 2; mt++) {
        const int row0 = bm + wm + mt * 16 + (lane >> 2);
        const int row1 = row0 + 8;
#pragma unroll
        for (int nt = 0; nt < 4; nt++) {
            const int col = bn + wn + nt * 8 + cl;
            if (MODE == 0) {
                if (row0 < cnt) {
                    float2 o0{acc[mt][nt][0], acc[mt][nt][1]};
                    *(float2*)&C[(size_t)row0 * Ee + col] = o0;
                }
                if (row1 < cnt) {
                    float2 o1{acc[mt][nt][2], acc[mt][nt][3]};
                    *(float2*)&C[(size_t)row1 * Ee + col] = o1;
                }
            } else {
                if (row0 < cnt) {
                    float* p = &C[(size_t)g_qidx[row0] * Ee + col];
                    atomicAdd(p, acc[mt][nt][0]);
                    atomicAdd(p + 1, acc[mt][nt][1]);
                }
                if (row1 < cnt) {
                    float* p = &C[(size_t)g_qidx[row1] * Ee + col];
                    atomicAdd(p, acc[mt][nt][2]);
                    atomicAdd(p + 1, acc[mt][nt][3]);
                }
            }
        }
    }
}

// batched QKV projection GEMM: z = 0 Q(softmax), 1 K(softmax), 2 V(plain)
__global__ __launch_bounds__(256, 3) void tgemm_qkv(
    const float* __restrict__ bq, const float* __restrict__ bk,
    const float* __restrict__ bv)
{
    extern __shared__ __align__(128) char smraw[];
    const int z = blockIdx.z;
    const int cnt = (z == 0) ? g_qoff[4] : g_koff[4];
    const int bm = blockIdx.y * 128;
    if (bm >= cnt) return;
    const int bn = blockIdx.x * 64;
    const __nv_bfloat16* Ahi = (z == 0) ? g_Qhi : (z == 1) ? g_Khi : g_Vhi;
    const __nv_bfloat16* Alo = (z == 0) ? g_Qlo : (z == 1) ? g_Klo : g_Vlo;
    const __nv_bfloat16* Bhi = (z == 0) ? g_Wqhi : (z == 1) ? g_Wkhi : g_Wvhi;
    const __nv_bfloat16* Blo = (z == 0) ? g_Wqlo : (z == 1) ? g_Wklo : g_Wvlo;
    const float* bias = (z == 0) ? bq : (z == 1) ? bk : bv;
    float* C = (z == 0) ? g_QH : (z == 1) ? g_KH : g_VH;
    gemm_body<0>(Ahi, Alo, Bhi, Blo, bias, C, cnt, bm, bn,
                 /*dosm=*/z != 2, 0, 96, smraw);
}

// final output-projection GEMM: split-K x2 (z = k-half), atomicAdd scatter.
__global__ __launch_bounds__(256, 3) void tgemm_fin(float* __restrict__ Cext)
{
    extern __shared__ __align__(128) char smraw[];
    const int cnt = g_qoff[4];
    const int bm = blockIdx.y * 128;
    if (bm >= cnt) return;
    const int s0lab = blockIdx.z * 48;
    gemm_body<2>(g_Qhi, g_Qlo, g_Wphi, g_Wplo, nullptr, Cext, cnt, bm,
                 blockIdx.x * 64, false, s0lab, s0lab + 48, smraw);
}

// =====================================================================
// misc: y=0 khmask rowsums (first 128 blocks), y=1 zero masked out rows,
//       y=2 bias-init unmasked out rows. grid (2048, 3).
// =====================================================================
__global__ __launch_bounds__(256) void misc_kernel(
    const float* __restrict__ Wk, const float* __restrict__ bk,
    const float* __restrict__ bp, float* __restrict__ out)
{
    const int y = blockIdx.y;
    if (y == 0) {
        if (blockIdx.x >= 128) return;
        const int r = blockIdx.x * 8 + (threadIdx.x >> 5);
        const int lane = threadIdx.x & 31;
        float s = 0.f;
        for (int e = lane; e < Ee; e += 32) s += Wk[(size_t)r * Ee + e];
#pragma unroll
        for (int o = 16; o; o >>= 1) s += __shfl_xor_sync(0xffffffffu, s, o);
        if (lane == 0) g_mvec[r] = -1e9f * s + bk[r];
    } else if (y == 1) {
        const int row = blockIdx.x * 8 + (threadIdx.x >> 5);
        if (g_qm[row]) return;
        const int lane = threadIdx.x & 31;
        const float4 z{0.f, 0.f, 0.f, 0.f};
        float4* o = (float4*)(out + (size_t)row * Ee);
#pragma unroll
        for (int j = 0; j < 8; j++) o[lane + j * 32] = z;
    } else {
        const int ci = blockIdx.x * 8 + (threadIdx.x >> 5);
        if (ci >= g_qoff[4]) return;
        const int row = g_qidx[ci];
        const int lane = threadIdx.x & 31;
        float4* o = (float4*)(out + (size_t)row * Ee);
        const float4* b = (const float4*)bp;
#pragma unroll
        for (int j = 0; j < 8; j++) o[lane + j * 32] = b[lane + j * 32];
    }
}

// =====================================================================
// init ctx/kcum with analytic masked-row corrections (local khm softmax)
// =====================================================================
__global__ void init_ctx(const float* __restrict__ bv)
{
    const int bh = blockIdx.x;
    const int b = bh >> 4, h = bh & 15;
    __shared__ float khm[Dd];
    if (threadIdx.x == 0) {
        float mx = -3.4e38f;
        for (int d = 0; d < Dd; d++) mx = fmaxf(mx, g_mvec[h * Dd + d]);
        float sm = 0.f;
        for (int d = 0; d < Dd; d++) sm += expf(g_mvec[h * Dd + d] - mx);
        const float inv = 1.f / sm;
        for (int d = 0; d < Dd; d++) khm[d] = expf(g_mvec[h * Dd + d] - mx) * inv;
    }
    __syncthreads();
    const float nm = (float)(Ss - (g_koff[b + 1] - g_koff[b]));
    for (int i = threadIdx.x; i < Dd * Dd; i += 256) {
        const int d = i >> 6, e = i & 63;
        g_ctx[bh * Dd * Dd + i] = nm * khm[d] * bv[h * Dd + e];
    }
    if (threadIdx.x < 64)
        g_kcum[bh * Dd + threadIdx.x] = nm * khm[threadIdx.x];
}

// =====================================================================
// context over compacted per-batch segment; folds kcum.
// =====================================================================
__global__ __launch_bounds__(256) void context_kernel()
{
    const int bh = blockIdx.y;
    const int b = bh >> 4, h = bh & 15;
    const int base = g_koff[b];
    const int cntb = g_koff[b + 1] - base;
    const int s0 = blockIdx.x * 256;
    if (s0 >= cntb) return;

    __shared__ __align__(16) float kh[3][16][64];
    __shared__ __align__(16) float vh[3][16][64];

    const int tid  = threadIdx.x;
    const int dB   = (tid >> 4) * 4;
    const int eB   = (tid & 15) * 4;
    const int lrow = tid >> 4;
    const int lseg = tid & 15;
    const uint32_t kB = smem_u32(&kh[0][0][0]);
    const uint32_t vB = smem_u32(&vh[0][0][0]);

    auto issue = [&](int t, int st) {
        const int row = s0 + t * 16 + lrow;
        const uint32_t sz = (row < cntb) ? 16u : 0u;
        const int rc = (row < cntb) ? row : 0;
        const size_t g = ((size_t)(base + rc)) * Ee + h * Dd + lseg * 4;
        CP_ASYNC16P(kB + st * 4096 + lrow * 256 + lseg * 16, g_KH + g, sz);
        CP_ASYNC16P(vB + st * 4096 + lrow * 256 + lseg * 16, g_VH + g, sz);
        CP_COMMIT();
    };

    float acc[4][4];
#pragma unroll
    for (int i = 0; i < 4; i++)
#pragma unroll
        for (int l = 0; l < 4; l++) acc[i][l] = 0.f;
    float kcp[4] = {0.f, 0.f, 0.f, 0.f};

    issue(0, 0);
    issue(1, 1);
#pragma unroll 1
    for (int t = 0; t < 16; t++) {
        if (t < 15) { CP_WAIT(1); } else { CP_WAIT(0); }
        __syncthreads();
        const int st = t % 3;
#pragma unroll
        for (int j = 0; j < 16; j++) {
            const float4 kv = *(const float4*)&kh[st][j][dB];
            const float4 vv = *(const float4*)&vh[st][j][eB];
            kcp[0] += kv.x; kcp[1] += kv.y; kcp[2] += kv.z; kcp[3] += kv.w;
            acc[0][0] += kv.x * vv.x; acc[0][1] += kv.x * vv.y;
            acc[0][2] += kv.x * vv.z; acc[0][3] += kv.x * vv.w;
            acc[1][0] += kv.y * vv.x; acc[1][1] += kv.y * vv.y;
            acc[1][2] += kv.y * vv.z; acc[1][3] += kv.y * vv.w;
            acc[2][0] += kv.z * vv.x; acc[2][1] += kv.z * vv.y;
            acc[2][2] += kv.z * vv.z; acc[2][3] += kv.z * vv.w;
            acc[3][0] += kv.w * vv.x; acc[3][1] += kv.w * vv.y;
            acc[3][2] += kv.w * vv.z; acc[3][3] += kv.w * vv.w;
        }
        if (t + 2 < 16) issue(t + 2, (t + 2) % 3);
    }

    float* ctx = g_ctx + (size_t)bh * Dd * Dd;
#pragma unroll
    for (int i = 0; i < 4; i++)
#pragma unroll
        for (int l = 0; l < 4; l++)
            atomicAdd(&ctx[(dB + i) * Dd + eB + l], acc[i][l]);
    if ((tid & 15) == 0) {
#pragma unroll
        for (int i = 0; i < 4; i++)
            atomicAdd(&g_kcum[bh * Dd + dB + i], kcp[i]);
    }
}

// =====================================================================
// combine over compacted q rows; emits hi/lo bf16 into g_Qhi/g_Qlo.
// =====================================================================
__global__ __launch_bounds__(256) void combine_kernel()
{
    const int bh = blockIdx.y;
    const int b = bh >> 4, h = bh & 15;
    const int base = g_qoff[b];
    const int cntb = g_qoff[b + 1] - base;
    const int s0 = blockIdx.x * 128;
    if (s0 >= cntb) return;

    __shared__ float ctx[64][64];
    __shared__ float kc[64];
    for (int i = threadIdx.x; i < Dd * Dd; i += 256)
        ((float*)ctx)[i] = g_ctx[(size_t)bh * Dd * Dd + i];
    if (threadIdx.x < 64) kc[threadIdx.x] = g_kcum[bh * Dd + threadIdx.x];
    __syncthreads();

    const int warp = threadIdx.x >> 5, lane = threadIdx.x & 31;
    const int lim = (s0 + 128 < cntb) ? (s0 + 128) : cntb;
    for (int s = s0 + warp; s < lim; s += 8) {
        const size_t gi = ((size_t)(base + s)) * Ee + h * Dd;
        const float* p = g_QH + gi;
        const float q0 = p[lane], q1 = p[lane + 32];
        float dot = q0 * kc[lane] + q1 * kc[lane + 32];
#pragma unroll
        for (int o = 16; o; o >>= 1) dot += __shfl_xor_sync(0xffffffffu, dot, o);
        const float a = 1.f / dot;
        float o0 = 0.f, o1 = 0.f;
#pragma unroll
        for (int d = 0; d < 32; d++) {
            const float qd = __shfl_sync(0xffffffffu, q0, d);
            o0 += qd * ctx[d][lane];
            o1 += qd * ctx[d][lane + 32];
        }
#pragma unroll
        for (int d = 0; d < 32; d++) {
            const float qd = __shfl_sync(0xffffffffu, q1, d);
            o0 += qd * ctx[d + 32][lane];
            o1 += qd * ctx[d + 32][lane + 32];
        }
        const float r0 = o0 * a + q0;
        const float r1 = o1 * a + q1;
        __nv_bfloat16 h0 = __float2bfloat16(r0);
        __nv_bfloat16 h1 = __float2bfloat16(r1);
        g_Qhi[gi + lane]      = h0;
        g_Qhi[gi + lane + 32] = h1;
        g_Qlo[gi + lane]      = __float2bfloat16(r0 - __bfloat162float(h0));
        g_Qlo[gi + lane + 32] = __float2bfloat16(r1 - __bfloat162float(h1));
    }
}

// =====================================================================
extern "C" void kernel_launch(void* const* d_in, const int* in_sizes, int n_in,
                              void* d_out, int out_size)
{
    const float* q  = (const float*)d_in[0];
    const float* k  = (const float*)d_in[1];
    const float* v  = (const float*)d_in[2];
    const unsigned char* qm_raw = (const unsigned char*)d_in[3];
    const unsigned char* km_raw = (const unsigned char*)d_in[4];
    const float* Wq = (const float*)d_in[5];
    const float* bq = (const float*)d_in[6];
    const float* Wk = (const float*)d_in[7];
    const float* bk = (const float*)d_in[8];
    const float* Wv = (const float*)d_in[9];
    const float* bv = (const float*)d_in[10];
    const float* Wp = (const float*)d_in[11];
    const float* bp = (const float*)d_in[12];
    float* out = (float*)d_out;

    cudaFuncSetAttribute(tgemm_qkv, cudaFuncAttributeMaxDynamicSharedMemorySize, GEMM_SMEM);
    cudaFuncSetAttribute(tgemm_fin, cudaFuncAttributeMaxDynamicSharedMemorySize, GEMM_SMEM);

    // 1-2) masks + compaction lists
    norm_mask2<<<dim3(1, 2), 1024>>>(qm_raw, km_raw, Mtot);
    scan_kernel<<<1, 256>>>();

    // 3) all conversions in one launch
    conv_all<<<dim3(2048, 4), 256>>>(q, k, v, Wq, Wk, Wv, Wp);

    // 4) batched QKV GEMM (128x64 tiles, BK=32, 3 CTAs/SM)
    tgemm_qkv<<<dim3(16, 128, 3), 256, GEMM_SMEM>>>(bq, bk, bv);

    // 5-6) masked-row analytics + output base (bias / zeros), then ctx init
    misc_kernel<<<dim3(2048, 3), 256>>>(Wk, bk, bp, out);
    init_ctx<<<Bb * Hh, 256>>>(bv);

    // 7-8) linear-attention core
    context_kernel<<<dim3(16, Bb * Hh), 256>>>();
    combine_kernel<<<dim3(32, Bb * Hh), 256>>>();

    // 9) output projection: split-K x2, atomicAdd scatter onto bias base
    tgemm_fin<<<dim3(16, 128, 2), 256, GEMM_SMEM>>>(out);
}